// round 12
// baseline (speedup 1.0000x reference)
#include <cuda_runtime.h>
#include <cstdint>

#define B_   32
#define S_   2048
#define IN_  300
#define H_   16
#define D_   16
#define A_   64
#define NIT  20

#define NPTS  (B_ * S_)    // 65536
#define GBLK  128          // main blocks
#define GTPB  512          // threads/block: 16 warps/SM, 4/SMSP, single wave

typedef unsigned long long u64;

// ---- packed f32x2 helpers (sm_103a FFMA2 path) ----
__device__ __forceinline__ u64 pack2(float lo, float hi) {
    u64 r; asm("mov.b64 %0, {%1,%2};" : "=l"(r) : "f"(lo), "f"(hi)); return r;
}
__device__ __forceinline__ void unpack2(u64 v, float& lo, float& hi) {
    asm("mov.b64 {%0,%1}, %2;" : "=f"(lo), "=f"(hi) : "l"(v));
}
__device__ __forceinline__ u64 ffma2(u64 a, u64 b, u64 c) {
    u64 d; asm("fma.rn.f32x2 %0, %1, %2, %3;" : "=l"(d) : "l"(a), "l"(b), "l"(c)); return d;
}
__device__ __forceinline__ u64 fmul2(u64 a, u64 b) {
    u64 d; asm("mul.rn.f32x2 %0, %1, %2;" : "=l"(d) : "l"(a), "l"(b)); return d;
}
__device__ __forceinline__ u64 fadd2(u64 a, u64 b) {
    u64 d; asm("add.rn.f32x2 %0, %1, %2;" : "=l"(d) : "l"(a), "l"(b)); return d;
}
__device__ __forceinline__ float sqrt_ap(float x) {
    float r; asm("sqrt.approx.f32 %0, %1;" : "=f"(r) : "f"(x)); return r;
}
__device__ __forceinline__ float rcp_ap(float x) {
    float r; asm("rcp.approx.f32 %0, %1;" : "=f"(r) : "f"(x)); return r;
}

// ---- scratch (device globals: no allocs allowed) ----
__device__ float g_afp[GBLK * D_];   // per-block partial sums of final positions
__device__ float g_chgp[GBLK];       // per-block partial of squared last-iter deltas
__device__ float g_rec[B_ * IN_];    // decoder output per b

// ============================================================
// Fused: encoder (300->16 relu ->16) + 20 gravity iterations +
// block reductions. 128 blocks x 512 threads, ONE point/thread.
// Gravity dot split into two 4-deep chains (latency) and
// 0.1*GRAV folded into w (removes 8 fmul2/iter).
// ============================================================
__global__ void __launch_bounds__(GTPB) gda_main(
    const float* __restrict__ inputs,
    const float* __restrict__ enc_w1, const float* __restrict__ enc_b1,
    const float* __restrict__ enc_w2, const float* __restrict__ enc_b2,
    const float* __restrict__ attractors)
{
    __shared__ ulonglong2 s_w1[IN_ * 4];   // 300x16 f32 = 19200B
    __shared__ ulonglong2 s_att[A_ * 4];   // 64x16 f32  = 4096B
    __shared__ float s_asq[A_];            // |a|^2
    __shared__ float s_b1[H_], s_b2[D_], s_w2[H_ * D_];
    __shared__ float s_af[D_];
    __shared__ float s_chg;

    const int tid = threadIdx.x;
    {
        float* w1f = reinterpret_cast<float*>(s_w1);
        for (int i = tid; i < IN_ * H_; i += GTPB) w1f[i] = enc_w1[i];
        float* af = reinterpret_cast<float*>(s_att);
        for (int i = tid; i < A_ * D_; i += GTPB) af[i] = attractors[i];
        for (int i = tid; i < H_ * D_; i += GTPB) s_w2[i] = enc_w2[i];
        if (tid < H_) s_b1[tid] = enc_b1[tid];
        if (tid < D_) s_b2[tid] = enc_b2[tid];
        if (tid < D_) s_af[tid] = 0.f;
        if (tid == 0) s_chg = 0.f;
    }
    __syncthreads();
    if (tid < A_) {
        const float* a = reinterpret_cast<const float*>(s_att) + tid * D_;
        float q = 0.f;
        #pragma unroll
        for (int d = 0; d < D_; d++) q = fmaf(a[d], a[d], q);
        s_asq[tid] = q;
    }
    __syncthreads();

    const int p = blockIdx.x * GTPB + tid;

    // ---------------- encoder layer 1 (packed f32x2) ----------------
    u64 acc2[8];
    #pragma unroll
    for (int j = 0; j < 8; j++) acc2[j] = 0ull;
    const float4* row = reinterpret_cast<const float4*>(inputs + (size_t)p * IN_);
    for (int i = 0; i < IN_ / 4; i++) {
        float4 x = __ldg(row + i);
        const ulonglong2* wp = s_w1 + i * 16;
        u64 xb;
        xb = pack2(x.x, x.x);
        acc2[0] = ffma2(xb, wp[0].x, acc2[0]);  acc2[1] = ffma2(xb, wp[0].y, acc2[1]);
        acc2[2] = ffma2(xb, wp[1].x, acc2[2]);  acc2[3] = ffma2(xb, wp[1].y, acc2[3]);
        acc2[4] = ffma2(xb, wp[2].x, acc2[4]);  acc2[5] = ffma2(xb, wp[2].y, acc2[5]);
        acc2[6] = ffma2(xb, wp[3].x, acc2[6]);  acc2[7] = ffma2(xb, wp[3].y, acc2[7]);
        xb = pack2(x.y, x.y);
        acc2[0] = ffma2(xb, wp[4].x, acc2[0]);  acc2[1] = ffma2(xb, wp[4].y, acc2[1]);
        acc2[2] = ffma2(xb, wp[5].x, acc2[2]);  acc2[3] = ffma2(xb, wp[5].y, acc2[3]);
        acc2[4] = ffma2(xb, wp[6].x, acc2[4]);  acc2[5] = ffma2(xb, wp[6].y, acc2[5]);
        acc2[6] = ffma2(xb, wp[7].x, acc2[6]);  acc2[7] = ffma2(xb, wp[7].y, acc2[7]);
        xb = pack2(x.z, x.z);
        acc2[0] = ffma2(xb, wp[8].x,  acc2[0]); acc2[1] = ffma2(xb, wp[8].y,  acc2[1]);
        acc2[2] = ffma2(xb, wp[9].x,  acc2[2]); acc2[3] = ffma2(xb, wp[9].y,  acc2[3]);
        acc2[4] = ffma2(xb, wp[10].x, acc2[4]); acc2[5] = ffma2(xb, wp[10].y, acc2[5]);
        acc2[6] = ffma2(xb, wp[11].x, acc2[6]); acc2[7] = ffma2(xb, wp[11].y, acc2[7]);
        xb = pack2(x.w, x.w);
        acc2[0] = ffma2(xb, wp[12].x, acc2[0]); acc2[1] = ffma2(xb, wp[12].y, acc2[1]);
        acc2[2] = ffma2(xb, wp[13].x, acc2[2]); acc2[3] = ffma2(xb, wp[13].y, acc2[3]);
        acc2[4] = ffma2(xb, wp[14].x, acc2[4]); acc2[5] = ffma2(xb, wp[14].y, acc2[5]);
        acc2[6] = ffma2(xb, wp[15].x, acc2[6]); acc2[7] = ffma2(xb, wp[15].y, acc2[7]);
    }

    // ---------------- encoder layer 2 ----------------
    u64 p2[8];
    {
        float hv[H_];
        #pragma unroll
        for (int j = 0; j < 8; j++) {
            float lo, hi; unpack2(acc2[j], lo, hi);
            hv[2 * j]     = fmaxf(lo + s_b1[2 * j],     0.f);
            hv[2 * j + 1] = fmaxf(hi + s_b1[2 * j + 1], 0.f);
        }
        #pragma unroll
        for (int j = 0; j < 8; j++) {
            float v0 = s_b2[2 * j], v1 = s_b2[2 * j + 1];
            #pragma unroll
            for (int h = 0; h < H_; h++) {
                v0 = fmaf(hv[h], s_w2[h * D_ + 2 * j], v0);
                v1 = fmaf(hv[h], s_w2[h * D_ + 2 * j + 1], v1);
            }
            p2[j] = pack2(v0, v1);
        }
    }

    // ---------------- gravity: 20 iterations ----------------
    const u64 kneg1 = pack2(-1.f, -1.f);
    float chg = 0.f;

    for (int it = 0; it < NIT; it++) {
        u64 q2 = fmul2(p2[0], p2[0]);
        #pragma unroll
        for (int j = 1; j < 8; j++) q2 = ffma2(p2[j], p2[j], q2);
        float plo, phi; unpack2(q2, plo, phi);
        const float psq = plo + phi;

        u64 fa2[8];   // accumulates 0.1*GRAV * sum(rcp * a)
        #pragma unroll
        for (int j = 0; j < 8; j++) fa2[j] = 0ull;
        float wsum0 = 0.f, wsum1 = 0.f;   // accumulate 0.1*GRAV*rcp

        #pragma unroll 8
        for (int a = 0; a < A_; a++) {
            const ulonglong2* av = s_att + a * 4;
            ulonglong2 v0 = av[0], v1 = av[1], v2 = av[2], v3 = av[3];
            // two independent 4-deep dot chains
            u64 dA = fmul2(p2[0], v0.x);
            u64 dB = fmul2(p2[1], v0.y);
            dA = ffma2(p2[2], v1.x, dA);
            dB = ffma2(p2[3], v1.y, dB);
            dA = ffma2(p2[4], v2.x, dA);
            dB = ffma2(p2[5], v2.y, dB);
            dA = ffma2(p2[6], v3.x, dA);
            dB = ffma2(p2[7], v3.y, dB);
            u64 dsum = fadd2(dA, dB);
            float dl, dh; unpack2(dsum, dl, dh);
            float s = fmaf(-2.f, dl + dh, psq + s_asq[a]);
            s = fmaxf(s, 1e-12f);
            float dist = sqrt_ap(s) + 1e-6f;          // EXACT validated form
            float w = 0.001f * rcp_ap(dist * dist);   // 0.1 * GRAV folded in
            if (a & 1) wsum1 += w; else wsum0 += w;
            u64 wv = pack2(w, w);
            fa2[0] = ffma2(wv, v0.x, fa2[0]);
            fa2[1] = ffma2(wv, v0.y, fa2[1]);
            fa2[2] = ffma2(wv, v1.x, fa2[2]);
            fa2[3] = ffma2(wv, v1.y, fa2[3]);
            fa2[4] = ffma2(wv, v2.x, fa2[4]);
            fa2[5] = ffma2(wv, v2.y, fa2[5]);
            fa2[6] = ffma2(wv, v3.x, fa2[6]);
            fa2[7] = ffma2(wv, v3.y, fa2[7]);
        }

        const float c = fmaf(-1.0f, wsum0 + wsum1, 1.0f);  // new_p = c*p + fa
        const u64 c2 = pack2(c, c);
        if (it == NIT - 1) {
            u64 ch2 = 0ull;
            #pragma unroll
            for (int j = 0; j < 8; j++) {
                u64 np  = ffma2(p2[j], c2, fa2[j]);
                u64 dlt = ffma2(p2[j], kneg1, np);         // np - p
                ch2 = ffma2(dlt, dlt, ch2);
                p2[j] = np;
            }
            float cl, ch; unpack2(ch2, cl, ch);
            chg = cl + ch;
        } else {
            #pragma unroll
            for (int j = 0; j < 8; j++)
                p2[j] = ffma2(p2[j], c2, fa2[j]);
        }
    }

    // ---------------- reductions ----------------
    #pragma unroll
    for (int j = 0; j < 8; j++) {
        float lo, hi; unpack2(p2[j], lo, hi);
        #pragma unroll
        for (int off = 16; off; off >>= 1) {
            lo += __shfl_down_sync(0xffffffffu, lo, off);
            hi += __shfl_down_sync(0xffffffffu, hi, off);
        }
        if ((tid & 31) == 0) {
            atomicAdd(&s_af[2 * j], lo);
            atomicAdd(&s_af[2 * j + 1], hi);
        }
    }
    #pragma unroll
    for (int off = 16; off; off >>= 1)
        chg += __shfl_down_sync(0xffffffffu, chg, off);
    if ((tid & 31) == 0) atomicAdd(&s_chg, chg);
    __syncthreads();

    if (tid < D_) g_afp[blockIdx.x * D_ + tid] = s_af[tid];
    if (tid == 0) g_chgp[blockIdx.x]           = s_chg;
}

// ============================================================
// Decoder: reduce block partials -> af -> relu(16) -> 300,
// masses, final_change. 32 blocks (one per batch), 320 threads.
// ============================================================
__global__ void dec_k(const float* __restrict__ dec_w1, const float* __restrict__ dec_b1,
                      const float* __restrict__ dec_w2, const float* __restrict__ dec_b2,
                      const float* __restrict__ mass_w, const float* __restrict__ mass_b,
                      float* __restrict__ out)
{
    __shared__ float af[D_], h[H_];
    const int b = blockIdx.x, t = threadIdx.x;
    const int blk0 = b * (GBLK / B_);          // 4 main blocks per batch
    if (t < D_) {
        float v = 0.f;
        #pragma unroll
        for (int k = 0; k < GBLK / B_; k++)
            v += g_afp[(blk0 + k) * D_ + t];
        v *= (1.f / (float)S_);
        af[t] = v;
        out[b * D_ + t] = v;                   // attractor_field [B,16]
    }
    if (b == 0 && t >= 32 && t < 64) {
        const int lane = t - 32;
        float c = 0.f;
        for (int i = lane; i < GBLK; i += 32) c += g_chgp[i];
        #pragma unroll
        for (int off = 16; off; off >>= 1)
            c += __shfl_down_sync(0xffffffffu, c, off);
        if (lane == 0)
            out[B_ * D_ + B_ * S_ * IN_ + B_] = sqrtf(c);   // final_change
    }
    __syncthreads();
    if (t < H_) {
        float v = dec_b1[t];
        #pragma unroll
        for (int d = 0; d < D_; d++) v = fmaf(af[d], dec_w1[d * H_ + t], v);
        h[t] = fmaxf(v, 0.f);
    } else if (t == H_) {
        float m = mass_b[0];
        #pragma unroll
        for (int d = 0; d < D_; d++) m = fmaf(af[d], mass_w[d], m);
        out[B_ * D_ + B_ * S_ * IN_ + b] = 1.f / (1.f + expf(-m));   // masses [B,1]
    }
    __syncthreads();
    if (t < IN_) {
        float v = dec_b2[t];
        #pragma unroll
        for (int hh = 0; hh < H_; hh++) v = fmaf(h[hh], dec_w2[hh * IN_ + t], v);
        g_rec[b * IN_ + t] = v;
    }
}

// ============================================================
// Broadcast rec[b,:] to all S rows. Value held in a register;
// pure coalesced STG.128 stream.
// ============================================================
__global__ void fill_k(float4* __restrict__ out4)
{
    const int t     = threadIdx.x;           // 0..299
    const int chunk = blockIdx.x;            // 0..31
    const int b     = blockIdx.y;            // 0..31
    const int col   = t % 75;
    const int rowi  = t / 75;                // 0..3
    const float4 val = __ldg(reinterpret_cast<const float4*>(g_rec) + b * 75 + col);
    size_t idx = ((size_t)b * S_ + chunk * 64 + rowi) * 75 + col;
    #pragma unroll 8
    for (int i = 0; i < 16; i++) {           // 16 * 4 rows = 64 rows
        out4[idx] = val;
        idx += 300;
    }
}

extern "C" void kernel_launch(void* const* d_in, const int* in_sizes, int n_in,
                              void* d_out, int out_size)
{
    const float* inputs = (const float*)d_in[0];
    const float* enc_w1 = (const float*)d_in[1];
    const float* enc_b1 = (const float*)d_in[2];
    const float* enc_w2 = (const float*)d_in[3];
    const float* enc_b2 = (const float*)d_in[4];
    const float* attr   = (const float*)d_in[5];
    const float* dec_w1 = (const float*)d_in[6];
    const float* dec_b1 = (const float*)d_in[7];
    const float* dec_w2 = (const float*)d_in[8];
    const float* dec_b2 = (const float*)d_in[9];
    const float* mass_w = (const float*)d_in[10];
    const float* mass_b = (const float*)d_in[11];
    float* out = (float*)d_out;

    gda_main<<<GBLK, GTPB>>>(inputs, enc_w1, enc_b1, enc_w2, enc_b2, attr);
    dec_k<<<B_, 320>>>(dec_w1, dec_b1, dec_w2, dec_b2, mass_w, mass_b, out);
    dim3 fg(32, 32);
    fill_k<<<fg, 300>>>(reinterpret_cast<float4*>(out + B_ * D_));
}

// round 13
// speedup vs baseline: 1.1317x; 1.1317x over previous
#include <cuda_runtime.h>
#include <cstdint>

#define B_   32
#define S_   2048
#define IN_  300
#define H_   16
#define D_   16
#define A_   64
#define NIT  20
#define GRAV 0.01f

#define NPTS  (B_ * S_)    // 65536
#define GBLK  128          // main blocks
#define GTPB  512          // threads/block: 16 warps/SM, 4/SMSP, single wave

typedef unsigned long long u64;

// ---- packed f32x2 helpers (sm_103a FFMA2 path) ----
__device__ __forceinline__ u64 pack2(float lo, float hi) {
    u64 r; asm("mov.b64 %0, {%1,%2};" : "=l"(r) : "f"(lo), "f"(hi)); return r;
}
__device__ __forceinline__ void unpack2(u64 v, float& lo, float& hi) {
    asm("mov.b64 {%0,%1}, %2;" : "=f"(lo), "=f"(hi) : "l"(v));
}
__device__ __forceinline__ u64 ffma2(u64 a, u64 b, u64 c) {
    u64 d; asm("fma.rn.f32x2 %0, %1, %2, %3;" : "=l"(d) : "l"(a), "l"(b), "l"(c)); return d;
}
__device__ __forceinline__ u64 fmul2(u64 a, u64 b) {
    u64 d; asm("mul.rn.f32x2 %0, %1, %2;" : "=l"(d) : "l"(a), "l"(b)); return d;
}
__device__ __forceinline__ float sqrt_ap(float x) {
    float r; asm("sqrt.approx.f32 %0, %1;" : "=f"(r) : "f"(x)); return r;
}
__device__ __forceinline__ float rcp_ap(float x) {
    float r; asm("rcp.approx.f32 %0, %1;" : "=f"(r) : "f"(x)); return r;
}

// ---- attractors in constant memory: warp-uniform LDCU + UR operands,
// ---- freeing the smem port and dropping FFMA2 GPR-bank pressure ----
__constant__ ulonglong2 c_att[A_ * 4];   // 64 x 16 f32 = 4 KB

// ---- scratch (device globals: no allocs allowed) ----
__device__ float g_afp[GBLK * D_];   // per-block partial sums of final positions
__device__ float g_chgp[GBLK];       // per-block partial of squared last-iter deltas
__device__ float g_rec[B_ * IN_];    // decoder output per b

// ============================================================
// Fused: encoder (300->16 relu ->16) + 20 gravity iterations +
// block reductions. 128 blocks x 512 threads, ONE point/thread.
// Arithmetic verbatim from R11 (242.2us best); only the
// attractor operand source changed (smem -> constant).
// ============================================================
__global__ void __launch_bounds__(GTPB) gda_main(
    const float* __restrict__ inputs,
    const float* __restrict__ enc_w1, const float* __restrict__ enc_b1,
    const float* __restrict__ enc_w2, const float* __restrict__ enc_b2)
{
    __shared__ ulonglong2 s_w1[IN_ * 4];   // 300x16 f32 = 19200B
    __shared__ float s_asq[A_];            // |a|^2
    __shared__ float s_b1[H_], s_b2[D_], s_w2[H_ * D_];
    __shared__ float s_af[D_];
    __shared__ float s_chg;

    const int tid = threadIdx.x;
    {
        float* w1f = reinterpret_cast<float*>(s_w1);
        for (int i = tid; i < IN_ * H_; i += GTPB) w1f[i] = enc_w1[i];
        for (int i = tid; i < H_ * D_; i += GTPB) s_w2[i] = enc_w2[i];
        if (tid < H_) s_b1[tid] = enc_b1[tid];
        if (tid < D_) s_b2[tid] = enc_b2[tid];
        if (tid < D_) s_af[tid] = 0.f;
        if (tid == 0) s_chg = 0.f;
    }
    if (tid < A_) {
        const float* a = reinterpret_cast<const float*>(c_att + tid * 4);
        float q = 0.f;
        #pragma unroll
        for (int d = 0; d < D_; d++) q = fmaf(a[d], a[d], q);
        s_asq[tid] = q;
    }
    __syncthreads();

    const int p = blockIdx.x * GTPB + tid;

    // ---------------- encoder layer 1 (packed f32x2) ----------------
    u64 acc2[8];
    #pragma unroll
    for (int j = 0; j < 8; j++) acc2[j] = 0ull;
    const float4* row = reinterpret_cast<const float4*>(inputs + (size_t)p * IN_);
    for (int i = 0; i < IN_ / 4; i++) {
        float4 x = __ldg(row + i);
        const ulonglong2* wp = s_w1 + i * 16;
        u64 xb;
        xb = pack2(x.x, x.x);
        acc2[0] = ffma2(xb, wp[0].x, acc2[0]);  acc2[1] = ffma2(xb, wp[0].y, acc2[1]);
        acc2[2] = ffma2(xb, wp[1].x, acc2[2]);  acc2[3] = ffma2(xb, wp[1].y, acc2[3]);
        acc2[4] = ffma2(xb, wp[2].x, acc2[4]);  acc2[5] = ffma2(xb, wp[2].y, acc2[5]);
        acc2[6] = ffma2(xb, wp[3].x, acc2[6]);  acc2[7] = ffma2(xb, wp[3].y, acc2[7]);
        xb = pack2(x.y, x.y);
        acc2[0] = ffma2(xb, wp[4].x, acc2[0]);  acc2[1] = ffma2(xb, wp[4].y, acc2[1]);
        acc2[2] = ffma2(xb, wp[5].x, acc2[2]);  acc2[3] = ffma2(xb, wp[5].y, acc2[3]);
        acc2[4] = ffma2(xb, wp[6].x, acc2[4]);  acc2[5] = ffma2(xb, wp[6].y, acc2[5]);
        acc2[6] = ffma2(xb, wp[7].x, acc2[6]);  acc2[7] = ffma2(xb, wp[7].y, acc2[7]);
        xb = pack2(x.z, x.z);
        acc2[0] = ffma2(xb, wp[8].x,  acc2[0]); acc2[1] = ffma2(xb, wp[8].y,  acc2[1]);
        acc2[2] = ffma2(xb, wp[9].x,  acc2[2]); acc2[3] = ffma2(xb, wp[9].y,  acc2[3]);
        acc2[4] = ffma2(xb, wp[10].x, acc2[4]); acc2[5] = ffma2(xb, wp[10].y, acc2[5]);
        acc2[6] = ffma2(xb, wp[11].x, acc2[6]); acc2[7] = ffma2(xb, wp[11].y, acc2[7]);
        xb = pack2(x.w, x.w);
        acc2[0] = ffma2(xb, wp[12].x, acc2[0]); acc2[1] = ffma2(xb, wp[12].y, acc2[1]);
        acc2[2] = ffma2(xb, wp[13].x, acc2[2]); acc2[3] = ffma2(xb, wp[13].y, acc2[3]);
        acc2[4] = ffma2(xb, wp[14].x, acc2[4]); acc2[5] = ffma2(xb, wp[14].y, acc2[5]);
        acc2[6] = ffma2(xb, wp[15].x, acc2[6]); acc2[7] = ffma2(xb, wp[15].y, acc2[7]);
    }

    // ---------------- encoder layer 2 ----------------
    u64 p2[8];
    {
        float hv[H_];
        #pragma unroll
        for (int j = 0; j < 8; j++) {
            float lo, hi; unpack2(acc2[j], lo, hi);
            hv[2 * j]     = fmaxf(lo + s_b1[2 * j],     0.f);
            hv[2 * j + 1] = fmaxf(hi + s_b1[2 * j + 1], 0.f);
        }
        #pragma unroll
        for (int j = 0; j < 8; j++) {
            float v0 = s_b2[2 * j], v1 = s_b2[2 * j + 1];
            #pragma unroll
            for (int h = 0; h < H_; h++) {
                v0 = fmaf(hv[h], s_w2[h * D_ + 2 * j], v0);
                v1 = fmaf(hv[h], s_w2[h * D_ + 2 * j + 1], v1);
            }
            p2[j] = pack2(v0, v1);
        }
    }

    // ---------------- gravity: 20 iterations (R11 verbatim, c_att source) ----
    const u64 k01   = pack2(0.1f, 0.1f);
    const u64 kneg1 = pack2(-1.f, -1.f);
    float chg = 0.f;

    for (int it = 0; it < NIT; it++) {
        u64 q2 = fmul2(p2[0], p2[0]);
        #pragma unroll
        for (int j = 1; j < 8; j++) q2 = ffma2(p2[j], p2[j], q2);
        float plo, phi; unpack2(q2, plo, phi);
        const float psq = plo + phi;

        u64 fa2[8];
        #pragma unroll
        for (int j = 0; j < 8; j++) fa2[j] = 0ull;
        float wsum0 = 0.f, wsum1 = 0.f;

        #pragma unroll 8
        for (int a = 0; a < A_; a++) {
            const ulonglong2* av = c_att + a * 4;      // constant: LDCU/UR path
            ulonglong2 v0 = av[0], v1 = av[1], v2 = av[2], v3 = av[3];
            u64 d2 = fmul2(p2[0], v0.x);
            d2 = ffma2(p2[1], v0.y, d2);
            d2 = ffma2(p2[2], v1.x, d2);
            d2 = ffma2(p2[3], v1.y, d2);
            d2 = ffma2(p2[4], v2.x, d2);
            d2 = ffma2(p2[5], v2.y, d2);
            d2 = ffma2(p2[6], v3.x, d2);
            d2 = ffma2(p2[7], v3.y, d2);
            float dl, dh; unpack2(d2, dl, dh);
            float s = fmaf(-2.f, dl + dh, psq + s_asq[a]);
            s = fmaxf(s, 1e-12f);
            float dist = sqrt_ap(s) + 1e-6f;          // EXACT validated form
            float w = GRAV * rcp_ap(dist * dist);
            if (a & 1) wsum1 += w; else wsum0 += w;
            u64 wv = pack2(w, w);
            fa2[0] = ffma2(wv, v0.x, fa2[0]);
            fa2[1] = ffma2(wv, v0.y, fa2[1]);
            fa2[2] = ffma2(wv, v1.x, fa2[2]);
            fa2[3] = ffma2(wv, v1.y, fa2[3]);
            fa2[4] = ffma2(wv, v2.x, fa2[4]);
            fa2[5] = ffma2(wv, v2.y, fa2[5]);
            fa2[6] = ffma2(wv, v3.x, fa2[6]);
            fa2[7] = ffma2(wv, v3.y, fa2[7]);
        }

        const float c = fmaf(-0.1f, wsum0 + wsum1, 1.0f);  // new_p = c*p + 0.1*fa
        const u64 c2 = pack2(c, c);
        if (it == NIT - 1) {
            u64 ch2 = 0ull;
            #pragma unroll
            for (int j = 0; j < 8; j++) {
                u64 np  = ffma2(p2[j], c2, fmul2(fa2[j], k01));
                u64 dlt = ffma2(p2[j], kneg1, np);         // np - p
                ch2 = ffma2(dlt, dlt, ch2);
                p2[j] = np;
            }
            float cl, ch; unpack2(ch2, cl, ch);
            chg = cl + ch;
        } else {
            #pragma unroll
            for (int j = 0; j < 8; j++)
                p2[j] = ffma2(p2[j], c2, fmul2(fa2[j], k01));
        }
    }

    // ---------------- reductions ----------------
    #pragma unroll
    for (int j = 0; j < 8; j++) {
        float lo, hi; unpack2(p2[j], lo, hi);
        #pragma unroll
        for (int off = 16; off; off >>= 1) {
            lo += __shfl_down_sync(0xffffffffu, lo, off);
            hi += __shfl_down_sync(0xffffffffu, hi, off);
        }
        if ((tid & 31) == 0) {
            atomicAdd(&s_af[2 * j], lo);
            atomicAdd(&s_af[2 * j + 1], hi);
        }
    }
    #pragma unroll
    for (int off = 16; off; off >>= 1)
        chg += __shfl_down_sync(0xffffffffu, chg, off);
    if ((tid & 31) == 0) atomicAdd(&s_chg, chg);
    __syncthreads();

    if (tid < D_) g_afp[blockIdx.x * D_ + tid] = s_af[tid];
    if (tid == 0) g_chgp[blockIdx.x]           = s_chg;
}

// ============================================================
// Decoder: reduce block partials -> af -> relu(16) -> 300,
// masses, final_change. 32 blocks (one per batch), 320 threads.
// ============================================================
__global__ void dec_k(const float* __restrict__ dec_w1, const float* __restrict__ dec_b1,
                      const float* __restrict__ dec_w2, const float* __restrict__ dec_b2,
                      const float* __restrict__ mass_w, const float* __restrict__ mass_b,
                      float* __restrict__ out)
{
    __shared__ float af[D_], h[H_];
    const int b = blockIdx.x, t = threadIdx.x;
    const int blk0 = b * (GBLK / B_);          // 4 main blocks per batch
    if (t < D_) {
        float v = 0.f;
        #pragma unroll
        for (int k = 0; k < GBLK / B_; k++)
            v += g_afp[(blk0 + k) * D_ + t];
        v *= (1.f / (float)S_);
        af[t] = v;
        out[b * D_ + t] = v;                   // attractor_field [B,16]
    }
    if (b == 0 && t >= 32 && t < 64) {
        const int lane = t - 32;
        float c = 0.f;
        for (int i = lane; i < GBLK; i += 32) c += g_chgp[i];
        #pragma unroll
        for (int off = 16; off; off >>= 1)
            c += __shfl_down_sync(0xffffffffu, c, off);
        if (lane == 0)
            out[B_ * D_ + B_ * S_ * IN_ + B_] = sqrtf(c);   // final_change
    }
    __syncthreads();
    if (t < H_) {
        float v = dec_b1[t];
        #pragma unroll
        for (int d = 0; d < D_; d++) v = fmaf(af[d], dec_w1[d * H_ + t], v);
        h[t] = fmaxf(v, 0.f);
    } else if (t == H_) {
        float m = mass_b[0];
        #pragma unroll
        for (int d = 0; d < D_; d++) m = fmaf(af[d], mass_w[d], m);
        out[B_ * D_ + B_ * S_ * IN_ + b] = 1.f / (1.f + expf(-m));   // masses [B,1]
    }
    __syncthreads();
    if (t < IN_) {
        float v = dec_b2[t];
        #pragma unroll
        for (int hh = 0; hh < H_; hh++) v = fmaf(h[hh], dec_w2[hh * IN_ + t], v);
        g_rec[b * IN_ + t] = v;
    }
}

// ============================================================
// Broadcast rec[b,:] to all S rows. Value held in a register;
// pure coalesced STG.128 stream.
// ============================================================
__global__ void fill_k(float4* __restrict__ out4)
{
    const int t     = threadIdx.x;           // 0..299
    const int chunk = blockIdx.x;            // 0..31
    const int b     = blockIdx.y;            // 0..31
    const int col   = t % 75;
    const int rowi  = t / 75;                // 0..3
    const float4 val = __ldg(reinterpret_cast<const float4*>(g_rec) + b * 75 + col);
    size_t idx = ((size_t)b * S_ + chunk * 64 + rowi) * 75 + col;
    #pragma unroll 8
    for (int i = 0; i < 16; i++) {           // 16 * 4 rows = 64 rows
        out4[idx] = val;
        idx += 300;
    }
}

extern "C" void kernel_launch(void* const* d_in, const int* in_sizes, int n_in,
                              void* d_out, int out_size)
{
    const float* inputs = (const float*)d_in[0];
    const float* enc_w1 = (const float*)d_in[1];
    const float* enc_b1 = (const float*)d_in[2];
    const float* enc_w2 = (const float*)d_in[3];
    const float* enc_b2 = (const float*)d_in[4];
    const float* attr   = (const float*)d_in[5];
    const float* dec_w1 = (const float*)d_in[6];
    const float* dec_b1 = (const float*)d_in[7];
    const float* dec_w2 = (const float*)d_in[8];
    const float* dec_b2 = (const float*)d_in[9];
    const float* mass_w = (const float*)d_in[10];
    const float* mass_b = (const float*)d_in[11];
    float* out = (float*)d_out;

    // attractors -> constant bank (D2D async: graph-capture legal)
    cudaMemcpyToSymbolAsync(c_att, attr, A_ * D_ * sizeof(float), 0,
                            cudaMemcpyDeviceToDevice);

    gda_main<<<GBLK, GTPB>>>(inputs, enc_w1, enc_b1, enc_w2, enc_b2);
    dec_k<<<B_, 320>>>(dec_w1, dec_b1, dec_w2, dec_b2, mass_w, mass_b, out);
    dim3 fg(32, 32);
    fill_k<<<fg, 300>>>(reinterpret_cast<float4*>(out + B_ * D_));
}